// round 2
// baseline (speedup 1.0000x reference)
#include <cuda_runtime.h>

// ---------------- problem constants ----------------
#define S_N   100000
#define E_N   30000
#define K_N   1000
#define D_DIM 64
#define F_DIM 128
#define B_N   16384
#define NNZ_S 1600000
#define NNZ_E 480000
#define NNZ_K 32000
#define MOM   0.9f
#define LEAK  0.1f

// output layout (float32, flattened tuple)
#define OFF_STU  0LL
#define OFF_DIFF 16384000LL
#define OFF_DISC 32768000LL
#define OFF_KT   32784384LL
#define OFF_IMP  32912384LL

// ---------------- scratch (device globals; no allocation allowed) ----------------
__device__ __align__(16) float g_sA[S_N * D_DIM];
__device__ __align__(16) float g_sB[S_N * D_DIM];
__device__ __align__(16) float g_sAcc[S_N * D_DIM];
__device__ __align__(16) float g_eA[E_N * D_DIM];
__device__ __align__(16) float g_eB[E_N * D_DIM];
__device__ __align__(16) float g_eAcc[E_N * D_DIM];
__device__ __align__(16) float g_kA[K_N * D_DIM];
__device__ __align__(16) float g_kB[K_N * D_DIM];
__device__ __align__(16) float g_kAcc[K_N * D_DIM];
__device__ __align__(16) float g_lin[2 * B_N * F_DIM];   // student_leaky ++ diff_leaky

// ---------------- elementwise helpers (float4) ----------------
__global__ void copy2_k(const float4* __restrict__ src, float4* __restrict__ a,
                        float4* __restrict__ b, int n4) {
    int i = blockIdx.x * blockDim.x + threadIdx.x;
    if (i >= n4) return;
    float4 v = src[i];
    a[i] = v; b[i] = v;
}

__global__ void scale_copy_k(const float4* __restrict__ src, float4* __restrict__ dst, int n4) {
    int i = blockIdx.x * blockDim.x + threadIdx.x;
    if (i >= n4) return;
    float4 v = src[i];
    v.x *= MOM; v.y *= MOM; v.z *= MOM; v.w *= MOM;
    dst[i] = v;
}

__global__ void accum_k(float4* __restrict__ acc, const float4* __restrict__ src, int n4) {
    int i = blockIdx.x * blockDim.x + threadIdx.x;
    if (i >= n4) return;
    float4 a = acc[i], v = src[i];
    a.x += v.x; a.y += v.y; a.z += v.z; a.w += v.w;
    acc[i] = a;
}

// ---------------- COO SpMM via vector red (16 threads per nnz, one float4 each) ----
__global__ void spmm_atomic_k(const int* __restrict__ rows, const int* __restrict__ cols,
                              const float* __restrict__ vals, const float* __restrict__ x,
                              float* __restrict__ y, int nnz) {
    long long t = (long long)blockIdx.x * blockDim.x + threadIdx.x;
    int i = (int)(t >> 4);
    if (i >= nnz) return;
    int c = (int)(t & 15);
    float v   = __ldg(vals + i);
    int col   = __ldg(cols + i);
    int row   = __ldg(rows + i);
    float4 a  = __ldg((const float4*)(x + (size_t)col * D_DIM) + c);
    float4* dst = (float4*)(y + (size_t)row * D_DIM) + c;
    asm volatile("red.global.add.v4.f32 [%0], {%1,%2,%3,%4};"
                 :: "l"(dst), "f"(v * a.x), "f"(v * a.y), "f"(v * a.z), "f"(v * a.w)
                 : "memory");
}

// ---------------- gathered linear + leaky: out[r,f] = leaky(scale*src[idx[r]] . W[:,f] + b[f])
__global__ void gather_linear_leaky_k(const int* __restrict__ idx,
                                      const float* __restrict__ src,
                                      const float* __restrict__ W,     // [64,128] row-major
                                      const float* __restrict__ bias,  // [128]
                                      float* __restrict__ out,         // [nrows,128]
                                      int nrows, float scale) {
    __shared__ float Ws[D_DIM * F_DIM];   // 32 KB
    __shared__ float xs[32 * D_DIM];      // 8 KB
    int f  = threadIdx.x;                 // 0..127 (output column)
    int r0 = blockIdx.x * 32;

    { // load W (2048 float4, 128 threads -> 16 each)
        const float4* W4 = (const float4*)W;
        float4* Ws4 = (float4*)Ws;
#pragma unroll
        for (int i = 0; i < 16; i++) Ws4[i * F_DIM + f] = W4[i * F_DIM + f];
    }
    { // gather + scale 32 rows of x (512 float4)
        float4* xs4 = (float4*)xs;
        for (int i = f; i < 32 * 16; i += F_DIM) {
            int r  = i >> 4;
            int rr = r0 + r;
            float4 v = make_float4(0.f, 0.f, 0.f, 0.f);
            if (rr < nrows) {
                int g = idx ? idx[rr] : rr;
                v = ((const float4*)(src + (size_t)g * D_DIM))[i & 15];
                v.x *= scale; v.y *= scale; v.z *= scale; v.w *= scale;
            }
            xs4[i] = v;
        }
    }
    __syncthreads();

    float bf = bias[f];
#pragma unroll 1
    for (int rb = 0; rb < 32; rb += 4) {
        float a0 = bf, a1 = bf, a2 = bf, a3 = bf;
        const float* x0 = xs + (rb + 0) * D_DIM;
        const float* x1 = xs + (rb + 1) * D_DIM;
        const float* x2 = xs + (rb + 2) * D_DIM;
        const float* x3 = xs + (rb + 3) * D_DIM;
#pragma unroll
        for (int d = 0; d < D_DIM; d++) {
            float w = Ws[d * F_DIM + f];
            a0 = fmaf(x0[d], w, a0);
            a1 = fmaf(x1[d], w, a1);
            a2 = fmaf(x2[d], w, a2);
            a3 = fmaf(x3[d], w, a3);
        }
        int m = r0 + rb;
        if (m + 0 < nrows) out[(size_t)(m + 0) * F_DIM + f] = a0 > 0.f ? a0 : LEAK * a0;
        if (m + 1 < nrows) out[(size_t)(m + 1) * F_DIM + f] = a1 > 0.f ? a1 : LEAK * a1;
        if (m + 2 < nrows) out[(size_t)(m + 2) * F_DIM + f] = a2 > 0.f ? a2 : LEAK * a2;
        if (m + 3 < nrows) out[(size_t)(m + 3) * F_DIM + f] = a3 > 0.f ? a3 : LEAK * a3;
    }
}

// ---------------- disc: sigmoid(0.25 * exer_acc[eid] . Wd + bd) ----------------
__global__ void disc_k(const int* __restrict__ eid, const float* __restrict__ eacc,
                       const float* __restrict__ Wd, const float* __restrict__ bd,
                       float* __restrict__ out, int B) {
    int b = blockIdx.x * blockDim.x + threadIdx.x;
    if (b >= B) return;
    const float4* x = (const float4*)(eacc + (size_t)__ldg(eid + b) * D_DIM);
    float s = 0.f;
#pragma unroll
    for (int d = 0; d < 16; d++) {
        float4 xv = __ldg(x + d);
        float4 wv = __ldg((const float4*)Wd + d);
        s += xv.x * wv.x + xv.y * wv.y + xv.z * wv.z + xv.w * wv.w;
    }
    s = 0.25f * s + bd[0];
    out[b] = 1.0f / (1.0f + expf(-s));
}

// ---------------- impact gather: out[b] = impact_emb[eid[b]] ----------------
__global__ void impact_k(const int* __restrict__ eid, const float* __restrict__ imp,
                         float* __restrict__ out, int B) {
    int t = blockIdx.x * blockDim.x + threadIdx.x;
    if (t >= B * 16) return;
    int b = t >> 4, c = t & 15;
    ((float4*)out)[(size_t)b * 16 + c] =
        __ldg((const float4*)(imp + (size_t)__ldg(eid + b) * D_DIM) + c);
}

// ---------------- big GEMM: C[M,N] = A[M,128] @ B[N,128]^T (fp32 SIMT) ------------
#define BM 64
#define BN 64
#define BK 16
__global__ void gemm_tn_k(const float* __restrict__ A, const float* __restrict__ Bm,
                          float* __restrict__ C, int M, int N, int Kd) {
    __shared__ float As[BK][BM + 1];
    __shared__ float Bs[BK][BN + 1];
    int tid = threadIdx.x;
    int tx = tid & 15, ty = tid >> 4;
    int bm = blockIdx.y * BM;
    int bn = blockIdx.x * BN;
    float acc[4][4] = {};

    int lr = tid >> 2;            // 0..63 : row within tile
    int lk = (tid & 3) * 4;       // 0,4,8,12 : k offset

    for (int kc = 0; kc < Kd; kc += BK) {
        { // load A tile (transposed store)
            float4 a = *(const float4*)(A + (size_t)(bm + lr) * Kd + kc + lk);
            As[lk + 0][lr] = a.x; As[lk + 1][lr] = a.y;
            As[lk + 2][lr] = a.z; As[lk + 3][lr] = a.w;
            int n = bn + lr;
            float4 b = make_float4(0.f, 0.f, 0.f, 0.f);
            if (n < N) b = *(const float4*)(Bm + (size_t)n * Kd + kc + lk);
            Bs[lk + 0][lr] = b.x; Bs[lk + 1][lr] = b.y;
            Bs[lk + 2][lr] = b.z; Bs[lk + 3][lr] = b.w;
        }
        __syncthreads();
#pragma unroll
        for (int k = 0; k < BK; k++) {
            float af[4], bf[4];
#pragma unroll
            for (int i = 0; i < 4; i++) af[i] = As[k][ty * 4 + i];
#pragma unroll
            for (int j = 0; j < 4; j++) bf[j] = Bs[k][tx * 4 + j];
#pragma unroll
            for (int i = 0; i < 4; i++)
#pragma unroll
                for (int j = 0; j < 4; j++)
                    acc[i][j] = fmaf(af[i], bf[j], acc[i][j]);
        }
        __syncthreads();
    }
#pragma unroll
    for (int i = 0; i < 4; i++) {
        int m = bm + ty * 4 + i;
        int nb = bn + tx * 4;
#pragma unroll
        for (int j = 0; j < 4; j++) {
            int n = nb + j;
            if (n < N) C[(size_t)m * N + n] = acc[i][j];
        }
    }
}

// ---------------- host orchestration ----------------
static inline int cdiv(long long a, int b) { return (int)((a + b - 1) / b); }

static void run_conv(const float* emb, const int* rows, const int* cols, const float* vals,
                     int n, int nnz, float* cur, float* nxt, float* acc) {
    int n4 = n * (D_DIM / 4);
    copy2_k<<<cdiv(n4, 256), 256>>>((const float4*)emb, (float4*)cur, (float4*)acc, n4);
    for (int l = 0; l < 3; l++) {
        scale_copy_k<<<cdiv(n4, 256), 256>>>((const float4*)cur, (float4*)nxt, n4);
        long long tw = (long long)nnz * 16;
        spmm_atomic_k<<<cdiv(tw, 256), 256>>>(rows, cols, vals, cur, nxt, nnz);
        accum_k<<<cdiv(n4, 256), 256>>>((float4*)acc, (const float4*)nxt, n4);
        float* t = cur; cur = nxt; nxt = t;
    }
}

extern "C" void kernel_launch(void* const* d_in, const int* in_sizes, int n_in,
                              void* d_out, int out_size) {
    const int*   student_id = (const int*)d_in[0];
    const int*   exercise_id= (const int*)d_in[1];
    // d_in[2] = q_mask (unused by the reference outputs)
    const float* stu_emb    = (const float*)d_in[3];
    const float* exer_emb   = (const float*)d_in[4];
    const float* know_emb   = (const float*)d_in[5];
    const float* impact_emb = (const float*)d_in[6];
    const int*   s_rows = (const int*)d_in[7];
    const int*   s_cols = (const int*)d_in[8];
    const float* s_vals = (const float*)d_in[9];
    const int*   e_rows = (const int*)d_in[10];
    const int*   e_cols = (const int*)d_in[11];
    const float* e_vals = (const float*)d_in[12];
    const int*   k_rows = (const int*)d_in[13];
    const int*   k_cols = (const int*)d_in[14];
    const float* k_vals = (const float*)d_in[15];
    const float* W_stu  = (const float*)d_in[16];
    const float* b_stu  = (const float*)d_in[17];
    const float* W_exer = (const float*)d_in[18];
    const float* b_exer = (const float*)d_in[19];
    const float* W_know = (const float*)d_in[20];
    const float* b_know = (const float*)d_in[21];
    const float* W_disc = (const float*)d_in[22];
    const float* b_disc = (const float*)d_in[23];

    float* out = (float*)d_out;

    float *sA, *sB, *sAcc, *eA, *eB, *eAcc, *kA, *kB, *kAcc, *lin;
    cudaGetSymbolAddress((void**)&sA, g_sA);
    cudaGetSymbolAddress((void**)&sB, g_sB);
    cudaGetSymbolAddress((void**)&sAcc, g_sAcc);
    cudaGetSymbolAddress((void**)&eA, g_eA);
    cudaGetSymbolAddress((void**)&eB, g_eB);
    cudaGetSymbolAddress((void**)&eAcc, g_eAcc);
    cudaGetSymbolAddress((void**)&kA, g_kA);
    cudaGetSymbolAddress((void**)&kB, g_kB);
    cudaGetSymbolAddress((void**)&kAcc, g_kAcc);
    cudaGetSymbolAddress((void**)&lin, g_lin);

    // Phase 1: graph convolutions (acc holds emb + c1 + c2 + c3; /4 folded downstream)
    run_conv(stu_emb,  s_rows, s_cols, s_vals, S_N, NNZ_S, sA, sB, sAcc);
    run_conv(exer_emb, e_rows, e_cols, e_vals, E_N, NNZ_E, eA, eB, eAcc);
    run_conv(know_emb, k_rows, k_cols, k_vals, K_N, NNZ_K, kA, kB, kAcc);

    // Phase 2: small linears
    // student_leaky -> lin[0 .. B*128), diff_leaky -> lin[B*128 .. 2B*128)
    gather_linear_leaky_k<<<B_N / 32, F_DIM>>>(student_id,  sAcc, W_stu,  b_stu,
                                               lin,                 B_N, 0.25f);
    gather_linear_leaky_k<<<B_N / 32, F_DIM>>>(exercise_id, eAcc, W_exer, b_exer,
                                               lin + (size_t)B_N * F_DIM, B_N, 0.25f);
    // knowledge_ts -> out[OFF_KT]
    gather_linear_leaky_k<<<cdiv(K_N, 32), F_DIM>>>(nullptr, kAcc, W_know, b_know,
                                                    out + OFF_KT, K_N, 0.25f);
    // disc_ts
    disc_k<<<cdiv(B_N, 256), 256>>>(exercise_id, eAcc, W_disc, b_disc, out + OFF_DISC, B_N);
    // knowledge_impact_ts
    impact_k<<<cdiv((long long)B_N * 16, 256), 256>>>(exercise_id, impact_emb,
                                                      out + OFF_IMP, B_N);

    // Phase 3: big GEMM — [2B,128] @ [1000,128]^T -> student_ts ++ diff_ts (contiguous)
    {
        dim3 grid(cdiv(K_N, BN), (2 * B_N) / BM);
        gemm_tn_k<<<grid, 256>>>(lin, out + OFF_KT, out + OFF_STU, 2 * B_N, K_N, F_DIM);
    }
}

// round 6
// speedup vs baseline: 1.1769x; 1.1769x over previous
#include <cuda_runtime.h>

// ---------------- problem constants ----------------
#define S_N   100000
#define E_N   30000
#define K_N   1000
#define D_DIM 64
#define F_DIM 128
#define B_N   16384
#define NNZ_S 1600000
#define NNZ_E 480000
#define NNZ_K 32000
#define MOM   0.9f
#define LEAK  0.1f

// output layout (float32, flattened tuple)
#define OFF_STU  0LL
#define OFF_DIFF 16384000LL
#define OFF_DISC 32768000LL
#define OFF_KT   32784384LL
#define OFF_IMP  32912384LL

// ---------------- scratch (device globals; no allocation allowed) ----------------
__device__ __align__(256) float g_sA[S_N * D_DIM];
__device__ __align__(256) float g_sB[S_N * D_DIM];
__device__ __align__(256) float g_sAcc[S_N * D_DIM];
__device__ __align__(256) float g_eA[E_N * D_DIM];
__device__ __align__(256) float g_eB[E_N * D_DIM];
__device__ __align__(256) float g_eAcc[E_N * D_DIM];
__device__ __align__(256) float g_kA[K_N * D_DIM];
__device__ __align__(256) float g_kB[K_N * D_DIM];
__device__ __align__(256) float g_kAcc[K_N * D_DIM];
__device__ __align__(256) float g_lin[2 * B_N * F_DIM];   // student_leaky ++ diff_leaky

// CSR scratch
__device__ int  g_cnt[S_N];            // shared counter scratch (max graph size)
__device__ int  g_cursor[S_N];         // scatter cursors (shared, builds are sequential)
__device__ int  g_start_s[S_N + 1];
__device__ int  g_start_e[E_N + 1];
__device__ int  g_start_k[K_N + 1];
__device__ __align__(16) int2 g_pack_s[NNZ_S];   // (col, val-bits)
__device__ __align__(16) int2 g_pack_e[NNZ_E];
__device__ __align__(16) int2 g_pack_k[NNZ_K];

static inline int cdiv(long long a, int b) { return (int)((a + b - 1) / b); }

// ---------------- CSR build ----------------
__global__ void zero_i_k(int* __restrict__ p, int n) {
    int i = blockIdx.x * blockDim.x + threadIdx.x;
    if (i < n) p[i] = 0;
}

__global__ void hist_k(const int* __restrict__ rows, int* __restrict__ cnt, int nnz) {
    int i = blockIdx.x * blockDim.x + threadIdx.x;
    if (i < nnz) atomicAdd(cnt + __ldg(rows + i), 1);
}

// single block, 1024 threads: exclusive scan of cnt[0..n) into start[] and cursor[]
__global__ void scan_k(const int* __restrict__ cnt, int* __restrict__ start,
                       int* __restrict__ cursor, int n) {
    __shared__ int tsum[1024];
    int t = threadIdx.x;
    int C = (n + 1023) >> 10;
    int lo = t * C, hi = min(lo + C, n);
    int s = 0;
    for (int i = lo; i < hi; i++) s += __ldg(cnt + i);
    tsum[t] = s;
    __syncthreads();
    for (int off = 1; off < 1024; off <<= 1) {
        int u = 0;
        if (t >= off) u = tsum[t - off];
        __syncthreads();
        tsum[t] += u;
        __syncthreads();
    }
    int run = tsum[t] - s;   // exclusive prefix for this chunk
    for (int i = lo; i < hi; i++) {
        int c = __ldg(cnt + i);
        start[i] = run; cursor[i] = run;
        run += c;
    }
    if (t == 1023) start[n] = tsum[1023];
}

__global__ void scatter_k(const int* __restrict__ rows, const int* __restrict__ cols,
                          const float* __restrict__ vals, int* __restrict__ cursor,
                          int2* __restrict__ pack, int nnz) {
    int i = blockIdx.x * blockDim.x + threadIdx.x;
    if (i >= nnz) return;
    int pos = atomicAdd(cursor + __ldg(rows + i), 1);
    pack[pos] = make_int2(__ldg(cols + i), __float_as_int(__ldg(vals + i)));
}

// ---------------- fused CSR conv layer: warp per row ----------------
// nxt[r] = sum_j v*x[col] + MOM*cur[r];  acc (+)= nxt[r]  (init: acc = cur + nxt)
__global__ void conv_layer_k(const int* __restrict__ start, const int2* __restrict__ pack,
                             const float* __restrict__ x, const float* __restrict__ cur,
                             float* __restrict__ nxt, float* __restrict__ acc,
                             int n, int initAcc) {
    int warp = (blockIdx.x * blockDim.x + threadIdx.x) >> 5;
    if (warp >= n) return;
    int lane = threadIdx.x & 31;
    int s0 = __ldg(start + warp), s1 = __ldg(start + warp + 1);
    float sx = 0.f, sy = 0.f;
#pragma unroll 4
    for (int j = s0; j < s1; j++) {
        int2 p = __ldg(pack + j);
        float v = __int_as_float(p.y);
        float2 xv = *(const float2*)(x + (size_t)p.x * D_DIM + lane * 2);
        sx = fmaf(v, xv.x, sx);
        sy = fmaf(v, xv.y, sy);
    }
    size_t off = (size_t)warp * D_DIM + lane * 2;
    float2 c2 = *(const float2*)(cur + off);
    sx = fmaf(MOM, c2.x, sx);
    sy = fmaf(MOM, c2.y, sy);
    *(float2*)(nxt + off) = make_float2(sx, sy);
    float2 a;
    if (initAcc) { a.x = c2.x + sx; a.y = c2.y + sy; }
    else { a = *(const float2*)(acc + off); a.x += sx; a.y += sy; }
    *(float2*)(acc + off) = a;
}

// ---------------- gathered linear + leaky ----------------
__global__ void gather_linear_leaky_k(const int* __restrict__ idx,
                                      const float* __restrict__ src,
                                      const float* __restrict__ W,     // [64,128]
                                      const float* __restrict__ bias,
                                      float* __restrict__ out,         // [nrows,128]
                                      int nrows, float scale) {
    __shared__ float Ws[D_DIM * F_DIM];
    __shared__ float xs[32 * D_DIM];
    int f  = threadIdx.x;
    int r0 = blockIdx.x * 32;
    {
        const float4* W4 = (const float4*)W;
        float4* Ws4 = (float4*)Ws;
#pragma unroll
        for (int i = 0; i < 16; i++) Ws4[i * F_DIM + f] = W4[i * F_DIM + f];
    }
    {
        float4* xs4 = (float4*)xs;
        for (int i = f; i < 32 * 16; i += F_DIM) {
            int r  = i >> 4;
            int rr = r0 + r;
            float4 v = make_float4(0.f, 0.f, 0.f, 0.f);
            if (rr < nrows) {
                int g = idx ? idx[rr] : rr;
                v = ((const float4*)(src + (size_t)g * D_DIM))[i & 15];
                v.x *= scale; v.y *= scale; v.z *= scale; v.w *= scale;
            }
            xs4[i] = v;
        }
    }
    __syncthreads();

    float bf = bias[f];
#pragma unroll 1
    for (int rb = 0; rb < 32; rb += 4) {
        float a0 = bf, a1 = bf, a2 = bf, a3 = bf;
        const float* x0 = xs + (rb + 0) * D_DIM;
        const float* x1 = xs + (rb + 1) * D_DIM;
        const float* x2 = xs + (rb + 2) * D_DIM;
        const float* x3 = xs + (rb + 3) * D_DIM;
#pragma unroll
        for (int d = 0; d < D_DIM; d++) {
            float w = Ws[d * F_DIM + f];
            a0 = fmaf(x0[d], w, a0);
            a1 = fmaf(x1[d], w, a1);
            a2 = fmaf(x2[d], w, a2);
            a3 = fmaf(x3[d], w, a3);
        }
        int m = r0 + rb;
        if (m + 0 < nrows) out[(size_t)(m + 0) * F_DIM + f] = a0 > 0.f ? a0 : LEAK * a0;
        if (m + 1 < nrows) out[(size_t)(m + 1) * F_DIM + f] = a1 > 0.f ? a1 : LEAK * a1;
        if (m + 2 < nrows) out[(size_t)(m + 2) * F_DIM + f] = a2 > 0.f ? a2 : LEAK * a2;
        if (m + 3 < nrows) out[(size_t)(m + 3) * F_DIM + f] = a3 > 0.f ? a3 : LEAK * a3;
    }
}

// ---------------- disc: sigmoid(0.25 * exer_acc[eid] . Wd + bd) ----------------
__global__ void disc_k(const int* __restrict__ eid, const float* __restrict__ eacc,
                       const float* __restrict__ Wd, const float* __restrict__ bd,
                       float* __restrict__ out, int B) {
    int b = blockIdx.x * blockDim.x + threadIdx.x;
    if (b >= B) return;
    const float4* x = (const float4*)(eacc + (size_t)__ldg(eid + b) * D_DIM);
    float s = 0.f;
#pragma unroll
    for (int d = 0; d < 16; d++) {
        float4 xv = __ldg(x + d);
        float4 wv = __ldg((const float4*)Wd + d);
        s += xv.x * wv.x + xv.y * wv.y + xv.z * wv.z + xv.w * wv.w;
    }
    s = 0.25f * s + bd[0];
    out[b] = 1.0f / (1.0f + expf(-s));
}

// ---------------- impact gather ----------------
__global__ void impact_k(const int* __restrict__ eid, const float* __restrict__ imp,
                         float* __restrict__ out, int B) {
    int t = blockIdx.x * blockDim.x + threadIdx.x;
    if (t >= B * 16) return;
    int b = t >> 4, c = t & 15;
    ((float4*)out)[(size_t)b * 16 + c] =
        __ldg((const float4*)(imp + (size_t)__ldg(eid + b) * D_DIM) + c);
}

// ---------------- big GEMM: C[M,N] = A[M,128] @ B[N,128]^T (fp32 SIMT 128x64) ------
#define BM 128
#define BN 64
#define BK 16
__global__ __launch_bounds__(256) void gemm_tn_k(const float* __restrict__ A,
                                                 const float* __restrict__ Bm,
                                                 float* __restrict__ C, int M, int N) {
    __shared__ float As[BK][BM + 4];
    __shared__ float Bs[BK][BN + 4];
    int tid = threadIdx.x;
    int bm = blockIdx.y * BM;
    int bn = blockIdx.x * BN;
    int tx = tid & 15;    // 16 col groups * 4
    int ty = tid >> 4;    // 16 row groups * 8
    float acc[8][4] = {};

    for (int kc = 0; kc < 128; kc += BK) {
#pragma unroll
        for (int u = 0; u < 2; u++) {   // A tile: 512 float4
            int idx = tid + u * 256;
            int r = idx >> 2, lk = (idx & 3) * 4;
            float4 a = *(const float4*)(A + (size_t)(bm + r) * 128 + kc + lk);
            As[lk + 0][r] = a.x; As[lk + 1][r] = a.y;
            As[lk + 2][r] = a.z; As[lk + 3][r] = a.w;
        }
        {   // B tile: 256 float4
            int r = tid >> 2, lk = (tid & 3) * 4;
            int n = bn + r;
            float4 b = make_float4(0.f, 0.f, 0.f, 0.f);
            if (n < N) b = *(const float4*)(Bm + (size_t)n * 128 + kc + lk);
            Bs[lk + 0][r] = b.x; Bs[lk + 1][r] = b.y;
            Bs[lk + 2][r] = b.z; Bs[lk + 3][r] = b.w;
        }
        __syncthreads();
#pragma unroll
        for (int k = 0; k < BK; k++) {
            float4 a0 = *(const float4*)&As[k][ty * 8 + 0];
            float4 a1 = *(const float4*)&As[k][ty * 8 + 4];
            float4 bv = *(const float4*)&Bs[k][tx * 4];
            float af[8] = {a0.x, a0.y, a0.z, a0.w, a1.x, a1.y, a1.z, a1.w};
            float bf[4] = {bv.x, bv.y, bv.z, bv.w};
#pragma unroll
            for (int i = 0; i < 8; i++)
#pragma unroll
                for (int j = 0; j < 4; j++)
                    acc[i][j] = fmaf(af[i], bf[j], acc[i][j]);
        }
        __syncthreads();
    }
#pragma unroll
    for (int i = 0; i < 8; i++) {
        int m = bm + ty * 8 + i;
        int n = bn + tx * 4;
        if (n + 4 <= N) {
            *(float4*)(C + (size_t)m * N + n) =
                make_float4(acc[i][0], acc[i][1], acc[i][2], acc[i][3]);
        } else {
#pragma unroll
            for (int j = 0; j < 4; j++)
                if (n + j < N) C[(size_t)m * N + n + j] = acc[i][j];
        }
    }
}

// ---------------- host orchestration ----------------
static void build_csr(const int* rows, const int* cols, const float* vals,
                      int n, int nnz, int* start, int2* pack, int* cnt, int* cursor) {
    zero_i_k<<<cdiv(n, 256), 256>>>(cnt, n);
    hist_k<<<cdiv(nnz, 256), 256>>>(rows, cnt, nnz);
    scan_k<<<1, 1024>>>(cnt, start, cursor, n);
    scatter_k<<<cdiv(nnz, 256), 256>>>(rows, cols, vals, cursor, pack, nnz);
}

static void run_conv(const float* emb, const int* start, const int2* pack,
                     int n, float* bufA, float* bufB, float* acc) {
    int blocks = cdiv(n, 8);   // 8 warps / block
    // layer 1: cur = emb, acc initialized to emb + layer1
    conv_layer_k<<<blocks, 256>>>(start, pack, emb, emb, bufA, acc, n, 1);
    // layer 2
    conv_layer_k<<<blocks, 256>>>(start, pack, bufA, bufA, bufB, acc, n, 0);
    // layer 3
    conv_layer_k<<<blocks, 256>>>(start, pack, bufB, bufB, bufA, acc, n, 0);
}

extern "C" void kernel_launch(void* const* d_in, const int* in_sizes, int n_in,
                              void* d_out, int out_size) {
    const int*   student_id  = (const int*)d_in[0];
    const int*   exercise_id = (const int*)d_in[1];
    const float* stu_emb     = (const float*)d_in[3];
    const float* exer_emb    = (const float*)d_in[4];
    const float* know_emb    = (const float*)d_in[5];
    const float* impact_emb  = (const float*)d_in[6];
    const int*   s_rows = (const int*)d_in[7];
    const int*   s_cols = (const int*)d_in[8];
    const float* s_vals = (const float*)d_in[9];
    const int*   e_rows = (const int*)d_in[10];
    const int*   e_cols = (const int*)d_in[11];
    const float* e_vals = (const float*)d_in[12];
    const int*   k_rows = (const int*)d_in[13];
    const int*   k_cols = (const int*)d_in[14];
    const float* k_vals = (const float*)d_in[15];
    const float* W_stu  = (const float*)d_in[16];
    const float* b_stu  = (const float*)d_in[17];
    const float* W_exer = (const float*)d_in[18];
    const float* b_exer = (const float*)d_in[19];
    const float* W_know = (const float*)d_in[20];
    const float* b_know = (const float*)d_in[21];
    const float* W_disc = (const float*)d_in[22];
    const float* b_disc = (const float*)d_in[23];

    float* out = (float*)d_out;

    float *sA, *sB, *sAcc, *eA, *eB, *eAcc, *kA, *kB, *kAcc, *lin;
    int *cnt, *cursor, *st_s, *st_e, *st_k;
    int2 *pk_s, *pk_e, *pk_k;
    cudaGetSymbolAddress((void**)&sA, g_sA);
    cudaGetSymbolAddress((void**)&sB, g_sB);
    cudaGetSymbolAddress((void**)&sAcc, g_sAcc);
    cudaGetSymbolAddress((void**)&eA, g_eA);
    cudaGetSymbolAddress((void**)&eB, g_eB);
    cudaGetSymbolAddress((void**)&eAcc, g_eAcc);
    cudaGetSymbolAddress((void**)&kA, g_kA);
    cudaGetSymbolAddress((void**)&kB, g_kB);
    cudaGetSymbolAddress((void**)&kAcc, g_kAcc);
    cudaGetSymbolAddress((void**)&lin, g_lin);
    cudaGetSymbolAddress((void**)&cnt, g_cnt);
    cudaGetSymbolAddress((void**)&cursor, g_cursor);
    cudaGetSymbolAddress((void**)&st_s, g_start_s);
    cudaGetSymbolAddress((void**)&st_e, g_start_e);
    cudaGetSymbolAddress((void**)&st_k, g_start_k);
    cudaGetSymbolAddress((void**)&pk_s, g_pack_s);
    cudaGetSymbolAddress((void**)&pk_e, g_pack_e);
    cudaGetSymbolAddress((void**)&pk_k, g_pack_k);

    // Phase 0: CSR builds (sequential; cnt/cursor scratch shared)
    build_csr(s_rows, s_cols, s_vals, S_N, NNZ_S, st_s, pk_s, cnt, cursor);
    build_csr(e_rows, e_cols, e_vals, E_N, NNZ_E, st_e, pk_e, cnt, cursor);
    build_csr(k_rows, k_cols, k_vals, K_N, NNZ_K, st_k, pk_k, cnt, cursor);

    // Phase 1: fused graph convolutions (acc = emb + c1 + c2 + c3; /4 folded downstream)
    run_conv(stu_emb,  st_s, pk_s, S_N, sA, sB, sAcc);
    run_conv(exer_emb, st_e, pk_e, E_N, eA, eB, eAcc);
    run_conv(know_emb, st_k, pk_k, K_N, kA, kB, kAcc);

    // Phase 2: small linears
    gather_linear_leaky_k<<<B_N / 32, F_DIM>>>(student_id,  sAcc, W_stu,  b_stu,
                                               lin,                 B_N, 0.25f);
    gather_linear_leaky_k<<<B_N / 32, F_DIM>>>(exercise_id, eAcc, W_exer, b_exer,
                                               lin + (size_t)B_N * F_DIM, B_N, 0.25f);
    gather_linear_leaky_k<<<cdiv(K_N, 32), F_DIM>>>(nullptr, kAcc, W_know, b_know,
                                                    out + OFF_KT, K_N, 0.25f);
    disc_k<<<cdiv(B_N, 256), 256>>>(exercise_id, eAcc, W_disc, b_disc, out + OFF_DISC, B_N);
    impact_k<<<cdiv((long long)B_N * 16, 256), 256>>>(exercise_id, impact_emb,
                                                      out + OFF_IMP, B_N);

    // Phase 3: big GEMM — [2B,128] @ [1000,128]^T -> student_ts ++ diff_ts (contiguous)
    {
        dim3 grid(cdiv(K_N, BN), (2 * B_N) / BM);
        gemm_tn_k<<<grid, 256>>>(lin, out + OFF_KT, out + OFF_STU, 2 * B_N, K_N);
    }
}

// round 9
// speedup vs baseline: 1.3586x; 1.1544x over previous
#include <cuda_runtime.h>

// ---------------- problem constants ----------------
#define S_N   100000
#define E_N   30000
#define K_N   1000
#define D_DIM 64
#define F_DIM 128
#define B_N   16384
#define NNZ_S 1600000
#define NNZ_E 480000
#define NNZ_K 32000
#define MOM   0.9f
#define LEAK  0.1f

// output layout (float32, flattened tuple)
#define OFF_STU  0LL
#define OFF_DIFF 16384000LL
#define OFF_DISC 32768000LL
#define OFF_KT   32784384LL
#define OFF_IMP  32912384LL

// blocks per conv segment (8 rows / block)
#define CBL_S 12500
#define CBL_E 3750
#define CBL_K 125

// ---------------- scratch (device globals; no allocation allowed) ----------------
__device__ __align__(256) float g_sA[S_N * D_DIM];
__device__ __align__(256) float g_sB[S_N * D_DIM];
__device__ __align__(256) float g_sAcc[S_N * D_DIM];
__device__ __align__(256) float g_eA[E_N * D_DIM];
__device__ __align__(256) float g_eB[E_N * D_DIM];
__device__ __align__(256) float g_eAcc[E_N * D_DIM];
__device__ __align__(256) float g_kA[K_N * D_DIM];
__device__ __align__(256) float g_kB[K_N * D_DIM];
__device__ __align__(256) float g_kAcc[K_N * D_DIM];
__device__ __align__(256) float g_lin[2 * B_N * F_DIM];

// CSR scratch (per-graph counters so all builds run concurrently)
__device__ int  g_cnt_s[S_N];
__device__ int  g_cnt_e[E_N];
__device__ int  g_cnt_k[K_N];
__device__ int  g_cur_s[S_N];
__device__ int  g_cur_e[E_N];
__device__ int  g_cur_k[K_N];
__device__ int  g_start_s[S_N + 1];
__device__ int  g_start_e[E_N + 1];
__device__ int  g_start_k[K_N + 1];
__device__ __align__(16) int2 g_pack_s[NNZ_S];
__device__ __align__(16) int2 g_pack_e[NNZ_E];
__device__ __align__(16) int2 g_pack_k[NNZ_K];

static inline int cdiv(long long a, int b) { return (int)((a + b - 1) / b); }

// ---------------- merged CSR build ----------------
__global__ void zero_all_k(int* __restrict__ cs, int* __restrict__ ce, int* __restrict__ ck) {
    int i = blockIdx.x * blockDim.x + threadIdx.x;
    if (i < S_N) cs[i] = 0;
    if (i < E_N) ce[i] = 0;
    if (i < K_N) ck[i] = 0;
}

__global__ void hist_all_k(const int* __restrict__ rs, int* __restrict__ cs,
                           const int* __restrict__ re, int* __restrict__ ce,
                           const int* __restrict__ rk, int* __restrict__ ck) {
    int i = blockIdx.x * blockDim.x + threadIdx.x;
    if (i < NNZ_S) {
        atomicAdd(cs + __ldg(rs + i), 1);
    } else if (i < NNZ_S + NNZ_E) {
        atomicAdd(ce + __ldg(re + (i - NNZ_S)), 1);
    } else if (i < NNZ_S + NNZ_E + NNZ_K) {
        atomicAdd(ck + __ldg(rk + (i - NNZ_S - NNZ_E)), 1);
    }
}

// 3 blocks: block b scans graph b's counts into start[] and cursor[]
__global__ void scan3_k(const int* __restrict__ cs, int* __restrict__ ss, int* __restrict__ us,
                        const int* __restrict__ ce, int* __restrict__ se, int* __restrict__ ue,
                        const int* __restrict__ ck, int* __restrict__ sk, int* __restrict__ uk) {
    __shared__ int tsum[1024];
    const int* cnt; int* start; int* cursor; int n;
    if (blockIdx.x == 0)      { cnt = cs; start = ss; cursor = us; n = S_N; }
    else if (blockIdx.x == 1) { cnt = ce; start = se; cursor = ue; n = E_N; }
    else                      { cnt = ck; start = sk; cursor = uk; n = K_N; }
    int t = threadIdx.x;
    int C = (n + 1023) >> 10;
    int lo = t * C, hi = min(lo + C, n);
    int s = 0;
    for (int i = lo; i < hi; i++) s += __ldg(cnt + i);
    tsum[t] = s;
    __syncthreads();
    for (int off = 1; off < 1024; off <<= 1) {
        int u = 0;
        if (t >= off) u = tsum[t - off];
        __syncthreads();
        tsum[t] += u;
        __syncthreads();
    }
    int run = tsum[t] - s;
    for (int i = lo; i < hi; i++) {
        int c = __ldg(cnt + i);
        start[i] = run; cursor[i] = run;
        run += c;
    }
    if (t == 1023) start[n] = tsum[1023];
}

__global__ void scatter_all_k(const int* __restrict__ rs, const int* __restrict__ cls,
                              const float* __restrict__ vs, int* __restrict__ us,
                              int2* __restrict__ ps,
                              const int* __restrict__ re, const int* __restrict__ cle,
                              const float* __restrict__ ve, int* __restrict__ ue,
                              int2* __restrict__ pe,
                              const int* __restrict__ rk, const int* __restrict__ clk,
                              const float* __restrict__ vk, int* __restrict__ uk,
                              int2* __restrict__ pk) {
    int i = blockIdx.x * blockDim.x + threadIdx.x;
    if (i < NNZ_S) {
        int pos = atomicAdd(us + __ldg(rs + i), 1);
        ps[pos] = make_int2(__ldg(cls + i), __float_as_int(__ldg(vs + i)));
    } else if (i < NNZ_S + NNZ_E) {
        int j = i - NNZ_S;
        int pos = atomicAdd(ue + __ldg(re + j), 1);
        pe[pos] = make_int2(__ldg(cle + j), __float_as_int(__ldg(ve + j)));
    } else if (i < NNZ_S + NNZ_E + NNZ_K) {
        int j = i - NNZ_S - NNZ_E;
        int pos = atomicAdd(uk + __ldg(rk + j), 1);
        pk[pos] = make_int2(__ldg(clk + j), __float_as_int(__ldg(vk + j)));
    }
}

// ---------------- merged conv layer (3 graphs, warp per row) ----------------
struct ConvSeg {
    const int*  start;
    const int2* pack;
    const float* x;     // layer input (== cur)
    float* nxt;
    float* acc;
    int n;
};

__global__ void conv_all_k(ConvSeg s0, ConvSeg s1, ConvSeg s2, int initAcc) {
    int b = blockIdx.x;
    ConvSeg seg;
    int rbase;
    if (b < CBL_S)               { seg = s0; rbase = b * 8; }
    else if (b < CBL_S + CBL_E)  { seg = s1; rbase = (b - CBL_S) * 8; }
    else                         { seg = s2; rbase = (b - CBL_S - CBL_E) * 8; }
    int row = rbase + (threadIdx.x >> 5);
    if (row >= seg.n) return;
    int lane = threadIdx.x & 31;
    int j0 = __ldg(seg.start + row), j1 = __ldg(seg.start + row + 1);
    float sx = 0.f, sy = 0.f;
#pragma unroll 4
    for (int j = j0; j < j1; j++) {
        int2 p = __ldg(seg.pack + j);
        float v = __int_as_float(p.y);
        float2 xv = *(const float2*)(seg.x + (size_t)p.x * D_DIM + lane * 2);
        sx = fmaf(v, xv.x, sx);
        sy = fmaf(v, xv.y, sy);
    }
    size_t off = (size_t)row * D_DIM + lane * 2;
    float2 c2 = *(const float2*)(seg.x + off);
    sx = fmaf(MOM, c2.x, sx);
    sy = fmaf(MOM, c2.y, sy);
    *(float2*)(seg.nxt + off) = make_float2(sx, sy);
    float2 a;
    if (initAcc) { a.x = c2.x + sx; a.y = c2.y + sy; }
    else { a = *(const float2*)(seg.acc + off); a.x += sx; a.y += sy; }
    *(float2*)(seg.acc + off) = a;
}

// ---------------- gathered linear + leaky ----------------
__global__ void gather_linear_leaky_k(const int* __restrict__ idx,
                                      const float* __restrict__ src,
                                      const float* __restrict__ W,
                                      const float* __restrict__ bias,
                                      float* __restrict__ out,
                                      int nrows, float scale) {
    __shared__ float Ws[D_DIM * F_DIM];
    __shared__ float xs[32 * D_DIM];
    int f  = threadIdx.x;
    int r0 = blockIdx.x * 32;
    {
        const float4* W4 = (const float4*)W;
        float4* Ws4 = (float4*)Ws;
#pragma unroll
        for (int i = 0; i < 16; i++) Ws4[i * F_DIM + f] = W4[i * F_DIM + f];
    }
    {
        float4* xs4 = (float4*)xs;
        for (int i = f; i < 32 * 16; i += F_DIM) {
            int r  = i >> 4;
            int rr = r0 + r;
            float4 v = make_float4(0.f, 0.f, 0.f, 0.f);
            if (rr < nrows) {
                int g = idx ? idx[rr] : rr;
                v = ((const float4*)(src + (size_t)g * D_DIM))[i & 15];
                v.x *= scale; v.y *= scale; v.z *= scale; v.w *= scale;
            }
            xs4[i] = v;
        }
    }
    __syncthreads();

    float bf = bias[f];
#pragma unroll 1
    for (int rb = 0; rb < 32; rb += 4) {
        float a0 = bf, a1 = bf, a2 = bf, a3 = bf;
        const float* x0 = xs + (rb + 0) * D_DIM;
        const float* x1 = xs + (rb + 1) * D_DIM;
        const float* x2 = xs + (rb + 2) * D_DIM;
        const float* x3 = xs + (rb + 3) * D_DIM;
#pragma unroll
        for (int d = 0; d < D_DIM; d++) {
            float w = Ws[d * F_DIM + f];
            a0 = fmaf(x0[d], w, a0);
            a1 = fmaf(x1[d], w, a1);
            a2 = fmaf(x2[d], w, a2);
            a3 = fmaf(x3[d], w, a3);
        }
        int m = r0 + rb;
        if (m + 0 < nrows) out[(size_t)(m + 0) * F_DIM + f] = a0 > 0.f ? a0 : LEAK * a0;
        if (m + 1 < nrows) out[(size_t)(m + 1) * F_DIM + f] = a1 > 0.f ? a1 : LEAK * a1;
        if (m + 2 < nrows) out[(size_t)(m + 2) * F_DIM + f] = a2 > 0.f ? a2 : LEAK * a2;
        if (m + 3 < nrows) out[(size_t)(m + 3) * F_DIM + f] = a3 > 0.f ? a3 : LEAK * a3;
    }
}

// ---------------- disc + impact ----------------
__global__ void disc_k(const int* __restrict__ eid, const float* __restrict__ eacc,
                       const float* __restrict__ Wd, const float* __restrict__ bd,
                       float* __restrict__ out, int B) {
    int b = blockIdx.x * blockDim.x + threadIdx.x;
    if (b >= B) return;
    const float4* x = (const float4*)(eacc + (size_t)__ldg(eid + b) * D_DIM);
    float s = 0.f;
#pragma unroll
    for (int d = 0; d < 16; d++) {
        float4 xv = __ldg(x + d);
        float4 wv = __ldg((const float4*)Wd + d);
        s += xv.x * wv.x + xv.y * wv.y + xv.z * wv.z + xv.w * wv.w;
    }
    s = 0.25f * s + bd[0];
    out[b] = 1.0f / (1.0f + expf(-s));
}

__global__ void impact_k(const int* __restrict__ eid, const float* __restrict__ imp,
                         float* __restrict__ out, int B) {
    int t = blockIdx.x * blockDim.x + threadIdx.x;
    if (t >= B * 16) return;
    int b = t >> 4, c = t & 15;
    ((float4*)out)[(size_t)b * 16 + c] =
        __ldg((const float4*)(imp + (size_t)__ldg(eid + b) * D_DIM) + c);
}

// ---------------- big GEMM with packed fma.rn.f32x2 ----------------
// C[M,N] = A[M,128] @ B[N,128]^T ; accumulators paired along M (free from As layout)
#define BM 128
#define BN 64
#define BK 16
__global__ __launch_bounds__(256) void gemm_tn_f32x2_k(const float* __restrict__ A,
                                                       const float* __restrict__ Bm,
                                                       float* __restrict__ C,
                                                       int M, int N) {
    __shared__ float As[BK][BM + 4];   // [k][m], (BM+4)*4 = 528B row stride (16B aligned)
    __shared__ float Bs[BK][BN + 4];   // [k][n], 272B row stride (16B aligned)
    int tid = threadIdx.x;
    int bm = blockIdx.y * BM;
    int bn = blockIdx.x * BN;
    int tx = tid & 15;    // 16 col groups * 4 cols
    int ty = tid >> 4;    // 16 row groups * 8 rows (= 4 m-pairs)

    unsigned long long acc2[4][4];     // [m-pair][col], each packs 2 fp32 (m, m+1)
#pragma unroll
    for (int i = 0; i < 4; i++)
#pragma unroll
        for (int j = 0; j < 4; j++) acc2[i][j] = 0ULL;

    for (int kc = 0; kc < 128; kc += BK) {
#pragma unroll
        for (int u = 0; u < 2; u++) {   // A tile: 512 float4
            int idx = tid + u * 256;
            int r = idx >> 2, lk = (idx & 3) * 4;
            float4 a = *(const float4*)(A + (size_t)(bm + r) * 128 + kc + lk);
            As[lk + 0][r] = a.x; As[lk + 1][r] = a.y;
            As[lk + 2][r] = a.z; As[lk + 3][r] = a.w;
        }
        {   // B tile: 256 float4
            int r = tid >> 2, lk = (tid & 3) * 4;
            int n = bn + r;
            float4 b = make_float4(0.f, 0.f, 0.f, 0.f);
            if (n < N) b = *(const float4*)(Bm + (size_t)n * 128 + kc + lk);
            Bs[lk + 0][r] = b.x; Bs[lk + 1][r] = b.y;
            Bs[lk + 2][r] = b.z; Bs[lk + 3][r] = b.w;
        }
        __syncthreads();
#pragma unroll
        for (int k = 0; k < BK; k++) {
            // A: 8 m-values = 4 packed pairs, loaded directly as 64-bit lanes
            ulonglong2 a01 = *(const ulonglong2*)&As[k][ty * 8 + 0];
            ulonglong2 a23 = *(const ulonglong2*)&As[k][ty * 8 + 4];
            unsigned long long a2[4] = {a01.x, a01.y, a23.x, a23.y};
            // B: 4 scalar cols, duplicated into both halves
            float4 bv = *(const float4*)&Bs[k][tx * 4];
            unsigned long long b2[4];
            {
                unsigned int u0 = __float_as_uint(bv.x), u1 = __float_as_uint(bv.y);
                unsigned int u2 = __float_as_uint(bv.z), u3 = __float_as_uint(bv.w);
                asm("mov.b64 %0, {%1, %1};" : "=l"(b2[0]) : "r"(u0));
                asm("mov.b64 %0, {%1, %1};" : "=l"(b2[1]) : "r"(u1));
                asm("mov.b64 %0, {%1, %1};" : "=l"(b2[2]) : "r"(u2));
                asm("mov.b64 %0, {%1, %1};" : "=l"(b2[3]) : "r"(u3));
            }
#pragma unroll
            for (int i = 0; i < 4; i++)
#pragma unroll
                for (int j = 0; j < 4; j++)
                    asm("fma.rn.f32x2 %0, %1, %2, %3;"
                        : "=l"(acc2[i][j])
                        : "l"(a2[i]), "l"(b2[j]), "l"(acc2[i][j]));
        }
        __syncthreads();
    }
    // epilogue: unpack pairs -> two rows per m-pair
#pragma unroll
    for (int i = 0; i < 4; i++) {
        float lo[4], hi[4];
#pragma unroll
        for (int j = 0; j < 4; j++) {
            unsigned int ul, uh;
            asm("mov.b64 {%0, %1}, %2;" : "=r"(ul), "=r"(uh) : "l"(acc2[i][j]));
            lo[j] = __uint_as_float(ul);
            hi[j] = __uint_as_float(uh);
        }
        int m0 = bm + ty * 8 + i * 2;
        int n  = bn + tx * 4;
        if (n + 4 <= N) {
            *(float4*)(C + (size_t)m0 * N + n)       = make_float4(lo[0], lo[1], lo[2], lo[3]);
            *(float4*)(C + (size_t)(m0 + 1) * N + n) = make_float4(hi[0], hi[1], hi[2], hi[3]);
        } else {
#pragma unroll
            for (int j = 0; j < 4; j++)
                if (n + j < N) {
                    C[(size_t)m0 * N + n + j]       = lo[j];
                    C[(size_t)(m0 + 1) * N + n + j] = hi[j];
                }
        }
    }
}

// ---------------- host orchestration ----------------
extern "C" void kernel_launch(void* const* d_in, const int* in_sizes, int n_in,
                              void* d_out, int out_size) {
    const int*   student_id  = (const int*)d_in[0];
    const int*   exercise_id = (const int*)d_in[1];
    const float* stu_emb     = (const float*)d_in[3];
    const float* exer_emb    = (const float*)d_in[4];
    const float* know_emb    = (const float*)d_in[5];
    const float* impact_emb  = (const float*)d_in[6];
    const int*   s_rows = (const int*)d_in[7];
    const int*   s_cols = (const int*)d_in[8];
    const float* s_vals = (const float*)d_in[9];
    const int*   e_rows = (const int*)d_in[10];
    const int*   e_cols = (const int*)d_in[11];
    const float* e_vals = (const float*)d_in[12];
    const int*   k_rows = (const int*)d_in[13];
    const int*   k_cols = (const int*)d_in[14];
    const float* k_vals = (const float*)d_in[15];
    const float* W_stu  = (const float*)d_in[16];
    const float* b_stu  = (const float*)d_in[17];
    const float* W_exer = (const float*)d_in[18];
    const float* b_exer = (const float*)d_in[19];
    const float* W_know = (const float*)d_in[20];
    const float* b_know = (const float*)d_in[21];
    const float* W_disc = (const float*)d_in[22];
    const float* b_disc = (const float*)d_in[23];

    float* out = (float*)d_out;

    float *sA, *sB, *sAcc, *eA, *eB, *eAcc, *kA, *kB, *kAcc, *lin;
    int *cs, *ce, *ck, *us, *ue, *uk, *st_s, *st_e, *st_k;
    int2 *pk_s, *pk_e, *pk_k;
    cudaGetSymbolAddress((void**)&sA, g_sA);
    cudaGetSymbolAddress((void**)&sB, g_sB);
    cudaGetSymbolAddress((void**)&sAcc, g_sAcc);
    cudaGetSymbolAddress((void**)&eA, g_eA);
    cudaGetSymbolAddress((void**)&eB, g_eB);
    cudaGetSymbolAddress((void**)&eAcc, g_eAcc);
    cudaGetSymbolAddress((void**)&kA, g_kA);
    cudaGetSymbolAddress((void**)&kB, g_kB);
    cudaGetSymbolAddress((void**)&kAcc, g_kAcc);
    cudaGetSymbolAddress((void**)&lin, g_lin);
    cudaGetSymbolAddress((void**)&cs, g_cnt_s);
    cudaGetSymbolAddress((void**)&ce, g_cnt_e);
    cudaGetSymbolAddress((void**)&ck, g_cnt_k);
    cudaGetSymbolAddress((void**)&us, g_cur_s);
    cudaGetSymbolAddress((void**)&ue, g_cur_e);
    cudaGetSymbolAddress((void**)&uk, g_cur_k);
    cudaGetSymbolAddress((void**)&st_s, g_start_s);
    cudaGetSymbolAddress((void**)&st_e, g_start_e);
    cudaGetSymbolAddress((void**)&st_k, g_start_k);
    cudaGetSymbolAddress((void**)&pk_s, g_pack_s);
    cudaGetSymbolAddress((void**)&pk_e, g_pack_e);
    cudaGetSymbolAddress((void**)&pk_k, g_pack_k);

    // Phase 0: merged CSR builds (4 launches total)
    zero_all_k<<<cdiv(S_N, 256), 256>>>(cs, ce, ck);
    {
        long long tot = (long long)NNZ_S + NNZ_E + NNZ_K;
        hist_all_k<<<cdiv(tot, 256), 256>>>(s_rows, cs, e_rows, ce, k_rows, ck);
        scan3_k<<<3, 1024>>>(cs, st_s, us, ce, st_e, ue, ck, st_k, uk);
        scatter_all_k<<<cdiv(tot, 256), 256>>>(s_rows, s_cols, s_vals, us, pk_s,
                                               e_rows, e_cols, e_vals, ue, pk_e,
                                               k_rows, k_cols, k_vals, uk, pk_k);
    }

    // Phase 1: merged conv layers (3 launches; acc = emb + c1 + c2 + c3)
    {
        int grid = CBL_S + CBL_E + CBL_K;
        ConvSeg s1{st_s, pk_s, stu_emb,  sA, sAcc, S_N};
        ConvSeg e1{st_e, pk_e, exer_emb, eA, eAcc, E_N};
        ConvSeg k1{st_k, pk_k, know_emb, kA, kAcc, K_N};
        conv_all_k<<<grid, 256>>>(s1, e1, k1, 1);
        ConvSeg s2{st_s, pk_s, sA, sB, sAcc, S_N};
        ConvSeg e2{st_e, pk_e, eA, eB, eAcc, E_N};
        ConvSeg k2{st_k, pk_k, kA, kB, kAcc, K_N};
        conv_all_k<<<grid, 256>>>(s2, e2, k2, 0);
        ConvSeg s3{st_s, pk_s, sB, sA, sAcc, S_N};
        ConvSeg e3{st_e, pk_e, eB, eA, eAcc, E_N};
        ConvSeg k3{st_k, pk_k, kB, kA, kAcc, K_N};
        conv_all_k<<<grid, 256>>>(s3, e3, k3, 0);
    }

    // Phase 2: small linears
    gather_linear_leaky_k<<<B_N / 32, F_DIM>>>(student_id,  sAcc, W_stu,  b_stu,
                                               lin,                 B_N, 0.25f);
    gather_linear_leaky_k<<<B_N / 32, F_DIM>>>(exercise_id, eAcc, W_exer, b_exer,
                                               lin + (size_t)B_N * F_DIM, B_N, 0.25f);
    gather_linear_leaky_k<<<cdiv(K_N, 32), F_DIM>>>(nullptr, kAcc, W_know, b_know,
                                                    out + OFF_KT, K_N, 0.25f);
    disc_k<<<cdiv(B_N, 256), 256>>>(exercise_id, eAcc, W_disc, b_disc, out + OFF_DISC, B_N);
    impact_k<<<cdiv((long long)B_N * 16, 256), 256>>>(exercise_id, impact_emb,
                                                      out + OFF_IMP, B_N);

    // Phase 3: big GEMM — [2B,128] @ [1000,128]^T -> student_ts ++ diff_ts
    {
        dim3 grid(cdiv(K_N, BN), (2 * B_N) / BM);
        gemm_tn_f32x2_k<<<grid, 256>>>(lin, out + OFF_KT, out + OFF_STU, 2 * B_N, K_N);
    }
}